// round 7
// baseline (speedup 1.0000x reference)
#include <cuda_runtime.h>
#include <cuda_bf16.h>

// Output = C_total * conv3x3(inp, k): the 1000-step LIF recurrence is linear for
// I in [0,9) (spike/reset clamps provably inactive), so it collapses to a scalar.
//
// R6: exact R1 inner loop (the empirical winner: simple dist-0 loads, 32 regs),
// but 64-thread blocks split along x -> 4352 blocks -> ~29.4 blocks/SM -> ~91%
// occupancy (R1 was grid-limited at 78.8%). Occupancy has been the single
// monotone predictor of kernel time across R1-R5.

#define TW    64    // threads per block (each handles 4 output columns)
#define ROWS  15    // output rows per block; 510 = 34 * 15 exactly
#define XCOLS 256   // output columns per block (2 x-blocks per row)

__global__ __launch_bounds__(TW)
void snn_conv_kernel(const float* __restrict__ inp,
                     const float* __restrict__ kw,
                     float* __restrict__ out,
                     float cscale)
{
    const int W  = 512;   // input width/height
    const int OW = 510;   // output width/height

    const int n  = blockIdx.y;
    const int y0 = (blockIdx.x >> 1) * ROWS;     // y0 <= 495; rows y0..y0+16 < 512
    const int xb = (blockIdx.x & 1) * XCOLS;     // 0 or 256
    const int x0 = xb + threadIdx.x * 4;         // first output column, 16B aligned

    // 3x3 weights with the LIF scalar folded in
    const float k00 = kw[0]*cscale, k01 = kw[1]*cscale, k02 = kw[2]*cscale;
    const float k10 = kw[3]*cscale, k11 = kw[4]*cscale, k12 = kw[5]*cscale;
    const float k20 = kw[6]*cscale, k21 = kw[7]*cscale, k22 = kw[8]*cscale;

    const float* base  = inp + (size_t)n * W * W;
    float*       obase = out + (size_t)n * OW * OW;

    const bool hasb     = (x0 + 4) < W;      // only the x0==508 thread lacks the tail pair
    const bool fullcols = (x0 + 3) < OW;     // x0==508 thread writes only 2 valid cols

    // Sliding 3-row register window, dist-0 (R1 structure -> 32 regs)
    float4 a0, a1;
    float2 b0, b1;
    {
        const float* r0 = base + (size_t)y0 * W + x0;
        const float* r1 = r0 + W;
        a0 = *(const float4*)r0;
        a1 = *(const float4*)r1;
        b0 = hasb ? *(const float2*)(r0 + 4) : make_float2(0.f, 0.f);
        b1 = hasb ? *(const float2*)(r1 + 4) : make_float2(0.f, 0.f);
    }

#pragma unroll
    for (int r = 0; r < ROWS; r++) {
        const int y = y0 + r;

        const float* r2p = base + (size_t)(y + 2) * W + x0;
        float4 a2 = *(const float4*)r2p;
        float2 b2 = hasb ? *(const float2*)(r2p + 4) : make_float2(0.f, 0.f);

        float s0 = k00*a0.x + k01*a0.y + k02*a0.z
                 + k10*a1.x + k11*a1.y + k12*a1.z
                 + k20*a2.x + k21*a2.y + k22*a2.z;
        float s1 = k00*a0.y + k01*a0.z + k02*a0.w
                 + k10*a1.y + k11*a1.z + k12*a1.w
                 + k20*a2.y + k21*a2.z + k22*a2.w;
        float s2 = k00*a0.z + k01*a0.w + k02*b0.x
                 + k10*a1.z + k11*a1.w + k12*b1.x
                 + k20*a2.z + k21*a2.w + k22*b2.x;
        float s3 = k00*a0.w + k01*b0.x + k02*b0.y
                 + k10*a1.w + k11*b1.x + k12*b1.y
                 + k20*a2.w + k21*b2.x + k22*b2.y;

        float* orow = obase + (size_t)y * OW + x0;
        // output pitch 510 -> only 8B alignment guaranteed
        *(float2*)(orow) = make_float2(s0, s1);
        if (fullcols)
            *(float2*)(orow + 2) = make_float2(s2, s3);

        a0 = a1; b0 = b1;
        a1 = a2; b1 = b2;
    }
}

extern "C" void kernel_launch(void* const* d_in, const int* in_sizes, int n_in,
                              void* d_out, int out_size)
{
    const float* inp = (const float*)d_in[0];   // (64,512,512,1) fp32
    const float* k   = (const float*)d_in[1];   // (3,3,1,1) fp32
    float* out = (float*)d_out;                 // (64,510,510,1) fp32

    // Closed-form LIF coefficient (double precision, host, once per capture).
    const double DT = 0.01, R = 3000.0, C = 10.0, NS = 1000.0;
    double v  = (R * 1.0) / (R * C) * DT;   // v0 = 1e-3
    double vt = v;
    for (int i = 0; i < 999; i++) {
        v  = v + (-v + R * 1.0) / (R * C) * DT;
        vt = (v + vt) / NS;
    }
    const float cscale = (float)vt;         // ~1.0008e-3

    dim3 block(TW);
    dim3 grid(2 * (510 / ROWS), 64);        // 68 x 64 = 4352 blocks, single wave
    snn_conv_kernel<<<grid, block>>>(inp, k, out, cscale);
}